// round 13
// baseline (speedup 1.0000x reference)
#include <cuda_runtime.h>
#include <cuda_fp16.h>
#include <cstdint>

#define NNODE 8192
#define NEDGE 253952

__device__ float  d_X  [NNODE * 64];
__device__ __half d_PQh[6 * NNODE * 256];      // [e*2+half][node][256] fp16
__device__ float  d_G  [3 * NEDGE];
__device__ float  d_AGGe[3 * NNODE * 256];     // per-expert partial agg
__device__ __half d_Wh[3 * 256 * 256];         // [e][n][k] fp16

__device__ __forceinline__ float lrelu(float v) { return fmaxf(v, 0.01f * v); }

__device__ __forceinline__ uint32_t smem_u32(const void* p) {
    uint32_t a;
    asm("{ .reg .u64 t; cvta.to.shared.u64 t, %1; cvt.u32.u64 %0, t; }" : "=r"(a) : "l"(p));
    return a;
}

#define CP_ASYNC16(dst, src) \
    asm volatile("cp.async.cg.shared.global [%0], [%1], 16;" :: "r"(dst), "l"(src) : "memory")
#define CP_COMMIT() asm volatile("cp.async.commit_group;" ::: "memory")
#define CP_WAIT(n)  asm volatile("cp.async.wait_group %0;" :: "n"(n) : "memory")

#define LDSM_X4(r, a) \
    asm volatile("ldmatrix.sync.aligned.m8n8.x4.shared.b16 {%0,%1,%2,%3}, [%4];" \
        : "=r"((r)[0]), "=r"((r)[1]), "=r"((r)[2]), "=r"((r)[3]) : "r"(a))
#define MMA16816(d, a, b) \
    asm volatile("mma.sync.aligned.m16n8k16.row.col.f32.f16.f16.f32 " \
        "{%0,%1,%2,%3}, {%4,%5,%6,%7}, {%8,%9}, {%0,%1,%2,%3};" \
        : "+f"((d)[0]), "+f"((d)[1]), "+f"((d)[2]), "+f"((d)[3]) \
        : "r"((a)[0]), "r"((a)[1]), "r"((a)[2]), "r"((a)[3]), "r"((b)[0]), "r"((b)[1]))

// ------------------------- k1x: node-layout transpose ----------------------
__global__ void k1x(const float4* __restrict__ in4) {
    int idx = blockIdx.x * blockDim.x + threadIdx.x;
    if (idx >= NNODE * 16) return;
    int n = idx >> 4, q = idx & 15;
    int b = n >> 11, t = (n >> 5) & 63, a = n & 31;
    ((float4*)d_X)[idx] = in4[(((b * 32 + a) * 64) + t) * 16 + q];
}

// ------------------------- k1g: edge gates ---------------------------------
__global__ void k1g(const float* __restrict__ state, const float4* __restrict__ rt4) {
    int idx = blockIdx.x * blockDim.x + threadIdx.x;
    if (idx >= NEDGE) return;
    int bt = idx / 992, r = idx - bt * 992;
    int b = bt >> 6, t = bt & 63;
    int rec = r / 31, j = r - rec * 31;
    int send = j + (j >= rec);
    const float4 st = *(const float4*)&state[(((b * 32 + send) * 64) + t) * 4];
    const float4* rt = rt4 + (b * 992 + r) * 4;
    float4 r0 = rt[0], r1 = rt[1], r2 = rt[2], r3 = rt[3];
    d_G[0 * NEDGE + idx] = st.x * r0.y + st.y * r1.y + st.z * r2.y + st.w * r3.y;
    d_G[1 * NEDGE + idx] = st.x * r0.z + st.y * r1.z + st.z * r2.z + st.w * r3.z;
    d_G[2 * NEDGE + idx] = st.x * r0.w + st.y * r1.w + st.z * r2.w + st.w * r3.w;
}

// ------------- k2: P/Q node GEMMs -> fp16 (64-row blocks, round-9) ---------
__global__ __launch_bounds__(256) void k2(const float* __restrict__ w1,
                                          const float* __restrict__ b1) {
    __shared__ float xs[64][64];
    int row0 = blockIdx.x * 64, tid = threadIdx.x;
    for (int i = tid; i < 64 * 64; i += 256) xs[i >> 6][i & 63] = d_X[row0 * 64 + i];
    __syncthreads();
    for (int chunk = 0; chunk < 6; ++chunk) {
        int e = chunk >> 1, half = chunk & 1;
        const float* W = w1 + ((size_t)((e + 1) * 128 + half * 64)) * 256;
        float acc[64];
#pragma unroll
        for (int m = 0; m < 64; ++m) acc[m] = 0.f;
#pragma unroll 2
        for (int k = 0; k < 64; ++k) {
            float w = W[k * 256 + tid];
#pragma unroll
            for (int m = 0; m < 64; ++m) acc[m] += xs[m][k] * w;
        }
        float bias = (half == 0) ? b1[(e + 1) * 256 + tid] : 0.f;
        __half* dst = d_PQh + ((size_t)chunk * NNODE + row0) * 256 + tid;
#pragma unroll
        for (int m = 0; m < 64; ++m) dst[m * 256] = __float2half(acc[m] + bias);
    }
}

// --------------- k2w: W2 transpose -> fp16 [e][n][k] -----------------------
__global__ void k2w(const float* __restrict__ w2) {
    __shared__ float tile[32][33];
    int e = blockIdx.z, kt = blockIdx.x * 32, nt = blockIdx.y * 32;
    int tx = threadIdx.x, ty = threadIdx.y;          // 32 x 8
#pragma unroll
    for (int r = 0; r < 4; ++r)
        tile[ty + r * 8][tx] = w2[((size_t)(e + 1) * 256 + kt + ty + r * 8) * 256 + nt + tx];
    __syncthreads();
#pragma unroll
    for (int r = 0; r < 4; ++r) {
        int n = nt + ty + r * 8;
        d_Wh[((size_t)e * 256 + n) * 256 + kt + tx] = __float2half(tile[tx][ty + r * 8]);
    }
}

// ------ k3i: N-split B-resident fp16 HMMA, 2 CTAs/SM (cross-CTA overlap) ---
// Grid = 3 experts x 48 groups x 2 N-halves = 288 CTAs x 256 thr, 2 CTAs/SM.
// Each CTA: B-half (128 cols x 256k) SMEM-resident; 43/42 quad-tiles;
// A (128x256 fp16) in two kc-chunk buffers, built from L2-hot fp16 P/Q.
// 8 warps = 4M x 2N, warp tile 32x64 (inner loop identical to k3g).
#define SB_B    0            // 128 x 528 = 67584
#define SB_A    67584        // 2 x (128 x 144) = 36864
#define SB_G    104448       // 2 x 512
#define SB_B2   105472       // 1024
#define K3I_SMEM 106496

__global__ __launch_bounds__(256, 2) void k3i(const float* __restrict__ b2) {
    extern __shared__ char smem[];
    uint32_t sb = smem_u32(smem);
    int tid = threadIdx.x, lane = tid & 31, wid = tid >> 5;
    int mwarp = wid >> 1, nwarp = wid & 1;
    int e = blockIdx.x / 96, rem = blockIdx.x % 96;
    int jb = rem >> 1, nh = rem & 1;
    int t0     = (jb < 32) ? jb * 43 : 32 * 43 + (jb - 32) * 42;
    int ntiles = (jb < 32) ? 43 : 42;

    float* g_s = (float*)(smem + SB_G);
    float* b2s = (float*)(smem + SB_B2);
    const __half* Pg = d_PQh + (size_t)(e * 2) * NNODE * 256;
    const __half* Qg = d_PQh + (size_t)(e * 2 + 1) * NNODE * 256;

    auto cvt = [](uint32_t pa, uint32_t qa) -> uint32_t {
        __half2 h = __hadd2(*(__half2*)&pa, *(__half2*)&qa);
        __half2 s = __hmul2(h, __float2half2_rn(0.01f));
        __half2 r = __hmax2(h, s);
        return *(uint32_t*)&r;
    };
    // build one kc chunk (64 k) of A for tile t into buffer ab
    auto buildA = [&](int t, int kc, int ab) {
        int m = tid >> 1, sub = tid & 1;             // 2 threads/row, 64B each
        int bt = t >> 3, a0 = (t & 7) * 4;
        int mq = m >> 5, jj = m & 31;
        int rec = a0 + mq;
        int send = (jj < 31) ? (jj + (jj >= rec)) : 0;   // dummy rows gated
        const uint4* P4 = (const uint4*)(Pg + (size_t)(bt * 32 + send) * 256
                                         + kc * 64 + sub * 32);
        const uint4* Q4 = (const uint4*)(Qg + (size_t)(bt * 32 + rec) * 256
                                         + kc * 64 + sub * 32);
        uint4* dst = (uint4*)(smem + SB_A + ab * 18432 + m * 144 + sub * 64);
#pragma unroll
        for (int q = 0; q < 4; ++q) {
            uint4 p = P4[q], qq = Q4[q];
            uint4 o;
            o.x = cvt(p.x, qq.x); o.y = cvt(p.y, qq.y);
            o.z = cvt(p.z, qq.z); o.w = cvt(p.w, qq.w);
            dst[q] = o;
        }
    };
    auto stageG = [&](int t) {
        if (tid < 128) {
            int bt = t >> 3, a0 = (t & 7) * 4;
            int grp = tid >> 5, jj = tid & 31;
            g_s[(t & 1) * 128 + tid] = (jj < 31)
                ? d_G[(size_t)e * NEDGE + bt * 992 + (a0 + grp) * 31 + jj] : 0.f;
        }
    };

    // ---- prologue: b2 (full 256), B-half resident, first A chunk + gates ----
    b2s[tid] = b2[(e + 1) * 256 + tid];
    {
        const __half* Wsrc = d_Wh + (size_t)e * 65536 + (size_t)nh * 128 * 256;
        for (int i = tid; i < 4096; i += 256) {
            int n = i >> 5, c = i & 31;
            CP_ASYNC16(sb + SB_B + (uint32_t)(n * 528 + c * 16),
                       (const char*)(Wsrc + n * 256 + c * 8));
        }
        CP_COMMIT();
    }
    buildA(t0, 0, 0);
    stageG(t0);
    CP_WAIT(0);
    __syncthreads();

    uint32_t a_base = sb + SB_A
                    + (uint32_t)(mwarp * 32 + (lane & 7) + ((lane >> 3) & 1) * 8) * 144u
                    + ((lane >> 4) & 1) * 16u;
    uint32_t b_base = sb + SB_B
                    + (uint32_t)(nwarp * 64 + (lane & 7) + ((lane >> 4) & 1) * 8) * 528u
                    + ((lane >> 3) & 1) * 16u;

    for (int ti = 0; ti < ntiles; ++ti) {
        int t = t0 + ti;
        int bt = t >> 3, a0 = (t & 7) * 4;
        bool more = (ti + 1 < ntiles);

        float acc[2][8][4];
#pragma unroll
        for (int ms = 0; ms < 2; ++ms)
#pragma unroll
            for (int ns = 0; ns < 8; ++ns)
#pragma unroll
                for (int c = 0; c < 4; ++c) acc[ms][ns][c] = 0.f;

#pragma unroll
        for (int kc = 0; kc < 4; ++kc) {
            // overlap: build next chunk (or next tile's chunk 0 + gates)
            if (kc < 3) {
                buildA(t, kc + 1, (kc + 1) & 1);
            } else if (more) {
                buildA(t + 1, 0, 0);         // buf0 free since kc==2's sync
                stageG(t + 1);               // parity (t+1)&1, not read by tile t
            }
            uint32_t a_l = a_base + (uint32_t)((kc & 1) * 18432);
#pragma unroll
            for (int ks = 0; ks < 4; ++ks) {
                uint32_t koff = (uint32_t)(ks * 32);
                uint32_t bkoff = (uint32_t)(kc * 128 + ks * 32);
                uint32_t af0[4], af1[4];
                LDSM_X4(af0, a_l + koff);
                LDSM_X4(af1, a_l + 16 * 144 + koff);
#pragma unroll
                for (int p = 0; p < 4; ++p) {
                    uint32_t bf[4];
                    LDSM_X4(bf, b_base + p * 8448 + bkoff);
                    MMA16816(acc[0][2 * p],     af0, bf);
                    MMA16816(acc[0][2 * p + 1], af0, bf + 2);
                    MMA16816(acc[1][2 * p],     af1, bf);
                    MMA16816(acc[1][2 * p + 1], af1, bf + 2);
                }
            }
            __syncthreads();
        }

        // ---- epilogue: bias + lrelu + gate, reduce 32 rows/warp ----
        {
            const float* gs = g_s + (t & 1) * 128;
            float g00 = gs[mwarp * 32 + (lane >> 2)];
            float g01 = gs[mwarp * 32 + (lane >> 2) + 8];
            float g10 = gs[mwarp * 32 + 16 + (lane >> 2)];
            float g11 = gs[mwarp * 32 + 24 + (lane >> 2)];
            int node = bt * 32 + a0 + mwarp;
#pragma unroll
            for (int nst = 0; nst < 8; ++nst) {
                int c0 = nh * 128 + nwarp * 64 + nst * 8 + (lane & 3) * 2;
                float b0v = b2s[c0], b1v = b2s[c0 + 1];
                float s0 = lrelu(acc[0][nst][0] + b0v) * g00 + lrelu(acc[0][nst][2] + b0v) * g01
                         + lrelu(acc[1][nst][0] + b0v) * g10 + lrelu(acc[1][nst][2] + b0v) * g11;
                float s1 = lrelu(acc[0][nst][1] + b1v) * g00 + lrelu(acc[0][nst][3] + b1v) * g01
                         + lrelu(acc[1][nst][1] + b1v) * g10 + lrelu(acc[1][nst][3] + b1v) * g11;
                s0 += __shfl_xor_sync(~0u, s0, 4);  s1 += __shfl_xor_sync(~0u, s1, 4);
                s0 += __shfl_xor_sync(~0u, s0, 8);  s1 += __shfl_xor_sync(~0u, s1, 8);
                s0 += __shfl_xor_sync(~0u, s0, 16); s1 += __shfl_xor_sync(~0u, s1, 16);
                if (lane < 4) {
                    float* dst = d_AGGe + ((size_t)e * NNODE + node) * 256 + c0;
                    dst[0] = s0; dst[1] = s1;
                }
            }
        }
        // no sync needed: next tile's buf0/g were written before kc==3's sync;
        // epilogue only read acc (regs), g_s parity t, b2s (const)
    }
}

// --------- k5: output MLP + residual (64-row blocks, round-9) --------------
#define K5_SMEM (64 * 320 * 4 + 64 * 256 * 4)   // aug + hbuf = 147456

__global__ __launch_bounds__(256) void k5(const float* __restrict__ fw1,
                                          const float* __restrict__ fb1,
                                          const float* __restrict__ fw2,
                                          const float* __restrict__ fb2,
                                          const float* __restrict__ fw3,
                                          const float* __restrict__ fb3,
                                          float* __restrict__ out) {
    extern __shared__ float sm5[];
    float* aug  = sm5;               // [64][320]
    float* hbuf = sm5 + 64 * 320;    // [64][256]
    int row0 = blockIdx.x * 64, tid = threadIdx.x;

    for (int i = tid; i < 64 * 64; i += 256)
        aug[(i >> 6) * 320 + (i & 63)] = d_X[row0 * 64 + i];
    for (int i = tid; i < 64 * 256; i += 256) {
        size_t base = (size_t)row0 * 256 + i;
        aug[(i >> 8) * 320 + 64 + (i & 255)] = d_AGGe[base]
                                             + d_AGGe[(size_t)NNODE * 256 + base]
                                             + d_AGGe[(size_t)2 * NNODE * 256 + base];
    }
    __syncthreads();

    {
        float acc[64];
#pragma unroll
        for (int m = 0; m < 64; ++m) acc[m] = 0.f;
#pragma unroll 2
        for (int k = 0; k < 320; ++k) {
            float w = fw1[k * 256 + tid];
#pragma unroll
            for (int m = 0; m < 64; ++m) acc[m] += aug[m * 320 + k] * w;
        }
        float b = fb1[tid];
#pragma unroll
        for (int m = 0; m < 64; ++m) hbuf[m * 256 + tid] = lrelu(acc[m] + b);
    }
    __syncthreads();

    {
        float acc[64];
#pragma unroll
        for (int m = 0; m < 64; ++m) acc[m] = 0.f;
#pragma unroll 2
        for (int k = 0; k < 256; ++k) {
            float w = fw2[k * 256 + tid];
#pragma unroll
            for (int m = 0; m < 64; ++m) acc[m] += hbuf[m * 256 + k] * w;
        }
        float b = fb2[tid];
#pragma unroll
        for (int m = 0; m < 64; ++m) aug[m * 320 + tid] = lrelu(acc[m] + b);
    }
    __syncthreads();

    {
        int c = tid & 63, sub = tid >> 6;       // 4 subs x 16 rows
        float acc3[16];
#pragma unroll
        for (int mm = 0; mm < 16; ++mm) acc3[mm] = 0.f;
#pragma unroll 2
        for (int k = 0; k < 256; ++k) {
            float w = fw3[k * 64 + c];
#pragma unroll
            for (int mm = 0; mm < 16; ++mm)
                acc3[mm] += aug[(sub * 16 + mm) * 320 + k] * w;
        }
        float b = fb3[c];
#pragma unroll
        for (int mm = 0; mm < 16; ++mm) {
            int n = row0 + sub * 16 + mm;
            int bb = n >> 11, t = (n >> 5) & 63, a = n & 31;
            if (t < 63)
                out[(((bb * 32 + a) * 63) + t) * 64 + c] = d_X[n * 64 + c] + acc3[mm] + b;
        }
    }
}

// ---------------------------------------------------------------------------
extern "C" void kernel_launch(void* const* d_in, const int* in_sizes, int n_in,
                              void* d_out, int out_size) {
    (void)in_sizes; (void)n_in; (void)out_size;
    const float* inputs    = (const float*)d_in[0];
    const float* state     = (const float*)d_in[1];
    const float* rel_type  = (const float*)d_in[2];
    const float* msg_fc1_w = (const float*)d_in[5];
    const float* msg_fc1_b = (const float*)d_in[6];
    const float* msg_fc2_w = (const float*)d_in[7];
    const float* msg_fc2_b = (const float*)d_in[8];
    const float* out_fc1_w = (const float*)d_in[9];
    const float* out_fc1_b = (const float*)d_in[10];
    const float* out_fc2_w = (const float*)d_in[11];
    const float* out_fc2_b = (const float*)d_in[12];
    const float* out_fc3_w = (const float*)d_in[13];
    const float* out_fc3_b = (const float*)d_in[14];
    float* out = (float*)d_out;

    k1x<<<(NNODE * 16 + 255) / 256, 256>>>((const float4*)inputs);
    k1g<<<(NEDGE + 255) / 256, 256>>>(state, (const float4*)rel_type);
    k2<<<NNODE / 64, 256>>>(msg_fc1_w, msg_fc1_b);
    k2w<<<dim3(8, 8, 3), dim3(32, 8)>>>(msg_fc2_w);

    cudaFuncSetAttribute(k3i, cudaFuncAttributeMaxDynamicSharedMemorySize, K3I_SMEM);
    k3i<<<288, 256, K3I_SMEM>>>(msg_fc2_b);

    cudaFuncSetAttribute(k5, cudaFuncAttributeMaxDynamicSharedMemorySize, K5_SMEM);
    k5<<<NNODE / 64, 256, K5_SMEM>>>(out_fc1_w, out_fc1_b, out_fc2_w, out_fc2_b,
                                     out_fc3_w, out_fc3_b, out);
}

// round 14
// speedup vs baseline: 1.1297x; 1.1297x over previous
#include <cuda_runtime.h>
#include <cuda_fp16.h>
#include <cstdint>

#define NNODE 8192
#define NEDGE 253952

__device__ float  d_X  [NNODE * 64];
__device__ __half d_PQh[6 * NNODE * 256];      // [e*2+half][node][256] fp16
__device__ float  d_G  [3 * NEDGE];
__device__ float  d_AGGe[3 * NNODE * 256];     // per-expert partial agg
__device__ __half d_Wh[3 * 256 * 256];         // [e][n][k] fp16

__device__ __forceinline__ float lrelu(float v) { return fmaxf(v, 0.01f * v); }

__device__ __forceinline__ uint32_t smem_u32(const void* p) {
    uint32_t a;
    asm("{ .reg .u64 t; cvta.to.shared.u64 t, %1; cvt.u32.u64 %0, t; }" : "=r"(a) : "l"(p));
    return a;
}

#define CP_ASYNC16(dst, src) \
    asm volatile("cp.async.cg.shared.global [%0], [%1], 16;" :: "r"(dst), "l"(src) : "memory")
#define CP_COMMIT() asm volatile("cp.async.commit_group;" ::: "memory")
#define CP_WAIT(n)  asm volatile("cp.async.wait_group %0;" :: "n"(n) : "memory")

#define LDSM_X4(r, a) \
    asm volatile("ldmatrix.sync.aligned.m8n8.x4.shared.b16 {%0,%1,%2,%3}, [%4];" \
        : "=r"((r)[0]), "=r"((r)[1]), "=r"((r)[2]), "=r"((r)[3]) : "r"(a))
#define MMA16816(d, a, b) \
    asm volatile("mma.sync.aligned.m16n8k16.row.col.f32.f16.f16.f32 " \
        "{%0,%1,%2,%3}, {%4,%5,%6,%7}, {%8,%9}, {%0,%1,%2,%3};" \
        : "+f"((d)[0]), "+f"((d)[1]), "+f"((d)[2]), "+f"((d)[3]) \
        : "r"((a)[0]), "r"((a)[1]), "r"((a)[2]), "r"((a)[3]), "r"((b)[0]), "r"((b)[1]))

// ------------------------- k1x: node-layout transpose ----------------------
__global__ void k1x(const float4* __restrict__ in4) {
    int idx = blockIdx.x * blockDim.x + threadIdx.x;
    if (idx >= NNODE * 16) return;
    int n = idx >> 4, q = idx & 15;
    int b = n >> 11, t = (n >> 5) & 63, a = n & 31;
    ((float4*)d_X)[idx] = in4[(((b * 32 + a) * 64) + t) * 16 + q];
}

// ------------------------- k1g: edge gates ---------------------------------
__global__ void k1g(const float* __restrict__ state, const float4* __restrict__ rt4) {
    int idx = blockIdx.x * blockDim.x + threadIdx.x;
    if (idx >= NEDGE) return;
    int bt = idx / 992, r = idx - bt * 992;
    int b = bt >> 6, t = bt & 63;
    int rec = r / 31, j = r - rec * 31;
    int send = j + (j >= rec);
    const float4 st = *(const float4*)&state[(((b * 32 + send) * 64) + t) * 4];
    const float4* rt = rt4 + (b * 992 + r) * 4;
    float4 r0 = rt[0], r1 = rt[1], r2 = rt[2], r3 = rt[3];
    d_G[0 * NEDGE + idx] = st.x * r0.y + st.y * r1.y + st.z * r2.y + st.w * r3.y;
    d_G[1 * NEDGE + idx] = st.x * r0.z + st.y * r1.z + st.z * r2.z + st.w * r3.z;
    d_G[2 * NEDGE + idx] = st.x * r0.w + st.y * r1.w + st.z * r2.w + st.w * r3.w;
}

// ------------- k2: P/Q node GEMMs -> fp16 (64-row blocks) ------------------
__global__ __launch_bounds__(256) void k2(const float* __restrict__ w1,
                                          const float* __restrict__ b1) {
    __shared__ float xs[64][64];
    int row0 = blockIdx.x * 64, tid = threadIdx.x;
    for (int i = tid; i < 64 * 64; i += 256) xs[i >> 6][i & 63] = d_X[row0 * 64 + i];
    __syncthreads();
    for (int chunk = 0; chunk < 6; ++chunk) {
        int e = chunk >> 1, half = chunk & 1;
        const float* W = w1 + ((size_t)((e + 1) * 128 + half * 64)) * 256;
        float acc[64];
#pragma unroll
        for (int m = 0; m < 64; ++m) acc[m] = 0.f;
#pragma unroll 2
        for (int k = 0; k < 64; ++k) {
            float w = W[k * 256 + tid];
#pragma unroll
            for (int m = 0; m < 64; ++m) acc[m] += xs[m][k] * w;
        }
        float bias = (half == 0) ? b1[(e + 1) * 256 + tid] : 0.f;
        __half* dst = d_PQh + ((size_t)chunk * NNODE + row0) * 256 + tid;
#pragma unroll
        for (int m = 0; m < 64; ++m) dst[m * 256] = __float2half(acc[m] + bias);
    }
}

// --------------- k2w: W2 transpose -> fp16 [e][n][k] -----------------------
__global__ void k2w(const float* __restrict__ w2) {
    __shared__ float tile[32][33];
    int e = blockIdx.z, kt = blockIdx.x * 32, nt = blockIdx.y * 32;
    int tx = threadIdx.x, ty = threadIdx.y;          // 32 x 8
#pragma unroll
    for (int r = 0; r < 4; ++r)
        tile[ty + r * 8][tx] = w2[((size_t)(e + 1) * 256 + kt + ty + r * 8) * 256 + nt + tx];
    __syncthreads();
#pragma unroll
    for (int r = 0; r < 4; ++r) {
        int n = nt + ty + r * 8;
        d_Wh[((size_t)e * 256 + n) * 256 + kt + tx] = __float2half(tile[tx][ty + r * 8]);
    }
}

// ------------------------- k3g: B-resident fp16 HMMA edge GEMM -------------
// Grid = 3 experts x 49 blocks (147 CTAs). Per expert: 2048 quad-tiles split
// 42/41 per block. B (256x256 fp16) resident in SMEM; P/Q staged via cp.async;
// A double-buffered per kc chunk (round-9 proven structure).
#define SB_B    0            // 256 x 528 = 135168
#define SB_A    135168       // 2 x 128 x 144 = 36864
#define SB_P    172032       // 2 x 32 x 528 = 33792
#define SB_Q    205824       // 2 x 4 x 528 = 4224
#define SB_G    210048       // 512
#define SB_B2   210560       // 1024
#define K3G_SMEM 211584

__global__ __launch_bounds__(512, 1) void k3g(const float* __restrict__ b2) {
    extern __shared__ char smem[];
    uint32_t sb = smem_u32(smem);
    int tid = threadIdx.x, lane = tid & 31, wid = tid >> 5;
    int mwarp = wid >> 2, nwarp = wid & 3;
    int e = blockIdx.x / 49, j = blockIdx.x % 49;
    int t0     = (j < 39) ? j * 42 : 39 * 42 + (j - 39) * 41;
    int ntiles = (j < 39) ? 42 : 41;

    float* g_s = (float*)(smem + SB_G);
    float* b2s = (float*)(smem + SB_B2);
    const __half* Pg = d_PQh + (size_t)(e * 2) * NNODE * 256;
    const __half* Qg = d_PQh + (size_t)(e * 2 + 1) * NNODE * 256;

    auto stageP = [&](int bt, int pb) {
        const __half* src = Pg + (size_t)bt * 32 * 256;
        for (int i = tid; i < 1024; i += 512) {
            int r = i >> 5, c = i & 31;
            CP_ASYNC16(sb + SB_P + (uint32_t)(pb * 16896 + r * 528 + c * 16),
                       (const char*)(src + r * 256 + c * 8));
        }
        CP_COMMIT();
    };
    auto stageQ = [&](int t, int qb) {
        int bt = t >> 3, a0 = (t & 7) * 4;
        const __half* src = Qg + (size_t)(bt * 32 + a0) * 256;
        if (tid < 128) {
            int r = tid >> 5, c = tid & 31;
            CP_ASYNC16(sb + SB_Q + (uint32_t)(qb * 2112 + r * 528 + c * 16),
                       (const char*)(src + r * 256 + c * 8));
        }
        CP_COMMIT();
    };
    auto stageG = [&](int t) {
        if (tid < 128) {
            int bt = t >> 3, a0 = (t & 7) * 4;
            int grp = tid >> 5, jj = tid & 31;
            g_s[tid] = (jj < 31)
                ? d_G[(size_t)e * NEDGE + bt * 992 + (a0 + grp) * 31 + jj] : 0.f;
        }
    };
    auto cvt = [](uint32_t pa, uint32_t qa) -> uint32_t {
        __half2 h = __hadd2(*(__half2*)&pa, *(__half2*)&qa);
        __half2 s = __hmul2(h, __float2half2_rn(0.01f));
        __half2 r = __hmax2(h, s);
        return *(uint32_t*)&r;
    };
    auto buildA = [&](int t, int kc, int ab, int pb, int qb) {
        int m = tid >> 2, sub = tid & 3;
        int a0 = (t & 7) * 4;
        int mq = m >> 5, jj = m & 31;
        int rec = a0 + mq;
        int send = (jj < 31) ? (jj + (jj >= rec)) : 0;   // dummy rows gated later
        const uint4* P4 = (const uint4*)(smem + SB_P + pb * 16896 + send * 528
                                         + kc * 128 + sub * 32);
        const uint4* Q4 = (const uint4*)(smem + SB_Q + qb * 2112 + mq * 528
                                         + kc * 128 + sub * 32);
        uint4 p0 = P4[0], p1 = P4[1], q0 = Q4[0], q1 = Q4[1];
        uint4 o0, o1;
        o0.x = cvt(p0.x, q0.x); o0.y = cvt(p0.y, q0.y);
        o0.z = cvt(p0.z, q0.z); o0.w = cvt(p0.w, q0.w);
        o1.x = cvt(p1.x, q1.x); o1.y = cvt(p1.y, q1.y);
        o1.z = cvt(p1.z, q1.z); o1.w = cvt(p1.w, q1.w);
        uint4* dst = (uint4*)(smem + SB_A + ab * 18432 + m * 144 + sub * 32);
        dst[0] = o0; dst[1] = o1;
    };

    // ---- prologue: b2, full B, first P/Q ----
    if (tid < 256) b2s[tid] = b2[(e + 1) * 256 + tid];
    {
        const __half* Wsrc = d_Wh + (size_t)e * 65536;
        for (int i = tid; i < 8192; i += 512) {
            int n = i >> 5, c = i & 31;
            CP_ASYNC16(sb + SB_B + (uint32_t)(n * 528 + c * 16),
                       (const char*)(Wsrc + n * 256 + c * 8));
        }
        CP_COMMIT();
    }
    int pb = 0;
    stageP(t0 >> 3, 0);
    stageQ(t0, 0);
    CP_WAIT(0);
    __syncthreads();

    for (int ti = 0; ti < ntiles; ++ti) {
        int t = t0 + ti, qb = ti & 1;
        int bt = t >> 3, a0 = (t & 7) * 4;
        buildA(t, 0, 0, pb, qb);
        stageG(t);
        __syncthreads();

        float acc[2][8][4];
#pragma unroll
        for (int ms = 0; ms < 2; ++ms)
#pragma unroll
            for (int ns = 0; ns < 8; ++ns)
#pragma unroll
                for (int c = 0; c < 4; ++c) acc[ms][ns][c] = 0.f;

        for (int kc = 0; kc < 4; ++kc) {
            if (kc < 3) {
                buildA(t, kc + 1, (kc + 1) & 1, pb, qb);
            } else if (ti + 1 < ntiles) {
                stageQ(t + 1, qb ^ 1);
                if (((t + 1) & 7) == 0) stageP((t + 1) >> 3, pb ^ 1);
            }
            uint32_t a_l = sb + SB_A + (uint32_t)((kc & 1) * 18432)
                         + (uint32_t)(mwarp * 32 + (lane & 7) + ((lane >> 3) & 1) * 8) * 144u
                         + ((lane >> 4) & 1) * 16u;
            uint32_t b_l = sb + SB_B
                         + (uint32_t)(nwarp * 64 + (lane & 7) + ((lane >> 4) & 1) * 8) * 528u
                         + (uint32_t)(kc * 128) + ((lane >> 3) & 1) * 16u;
#pragma unroll
            for (int ks = 0; ks < 4; ++ks) {
                uint32_t af0[4], af1[4];
                LDSM_X4(af0, a_l + ks * 32);
                LDSM_X4(af1, a_l + 16 * 144 + ks * 32);
#pragma unroll
                for (int p = 0; p < 4; ++p) {
                    uint32_t bf[4];
                    LDSM_X4(bf, b_l + p * 8448 + ks * 32);
                    MMA16816(acc[0][2 * p],     af0, bf);
                    MMA16816(acc[0][2 * p + 1], af0, bf + 2);
                    MMA16816(acc[1][2 * p],     af1, bf);
                    MMA16816(acc[1][2 * p + 1], af1, bf + 2);
                }
            }
            if (kc == 3) {
                float g00 = g_s[mwarp * 32 + (lane >> 2)];
                float g01 = g_s[mwarp * 32 + (lane >> 2) + 8];
                float g10 = g_s[mwarp * 32 + 16 + (lane >> 2)];
                float g11 = g_s[mwarp * 32 + 24 + (lane >> 2)];
                int node = bt * 32 + a0 + mwarp;
#pragma unroll
                for (int nst = 0; nst < 8; ++nst) {
                    int c0 = nwarp * 64 + nst * 8 + (lane & 3) * 2;
                    float b0v = b2s[c0], b1v = b2s[c0 + 1];
                    float s0 = lrelu(acc[0][nst][0] + b0v) * g00 + lrelu(acc[0][nst][2] + b0v) * g01
                             + lrelu(acc[1][nst][0] + b0v) * g10 + lrelu(acc[1][nst][2] + b0v) * g11;
                    float s1 = lrelu(acc[0][nst][1] + b1v) * g00 + lrelu(acc[0][nst][3] + b1v) * g01
                             + lrelu(acc[1][nst][1] + b1v) * g10 + lrelu(acc[1][nst][3] + b1v) * g11;
                    s0 += __shfl_xor_sync(~0u, s0, 4);  s1 += __shfl_xor_sync(~0u, s1, 4);
                    s0 += __shfl_xor_sync(~0u, s0, 8);  s1 += __shfl_xor_sync(~0u, s1, 8);
                    s0 += __shfl_xor_sync(~0u, s0, 16); s1 += __shfl_xor_sync(~0u, s1, 16);
                    if (lane < 4) {
                        float2 o; o.x = s0; o.y = s1;
                        *(float2*)(d_AGGe + ((size_t)e * NNODE + node) * 256 + c0) = o;
                    }
                }
                if (ti + 1 < ntiles) CP_WAIT(0);
            }
            __syncthreads();
        }
        if (((t + 1) & 7) == 0) pb ^= 1;
    }
}

// --------- k5: output MLP + residual (64-row blocks) -----------------------
#define K5_SMEM (64 * 320 * 4 + 64 * 256 * 4)   // aug + hbuf = 147456

__global__ __launch_bounds__(256) void k5(const float* __restrict__ fw1,
                                          const float* __restrict__ fb1,
                                          const float* __restrict__ fw2,
                                          const float* __restrict__ fb2,
                                          const float* __restrict__ fw3,
                                          const float* __restrict__ fb3,
                                          float* __restrict__ out) {
    extern __shared__ float sm5[];
    float* aug  = sm5;               // [64][320]
    float* hbuf = sm5 + 64 * 320;    // [64][256]
    int row0 = blockIdx.x * 64, tid = threadIdx.x;

    for (int i = tid; i < 64 * 64; i += 256)
        aug[(i >> 6) * 320 + (i & 63)] = d_X[row0 * 64 + i];
    for (int i = tid; i < 64 * 256; i += 256) {
        size_t base = (size_t)row0 * 256 + i;
        aug[(i >> 8) * 320 + 64 + (i & 255)] = d_AGGe[base]
                                             + d_AGGe[(size_t)NNODE * 256 + base]
                                             + d_AGGe[(size_t)2 * NNODE * 256 + base];
    }
    __syncthreads();

    {
        float acc[64];
#pragma unroll
        for (int m = 0; m < 64; ++m) acc[m] = 0.f;
#pragma unroll 2
        for (int k = 0; k < 320; ++k) {
            float w = fw1[k * 256 + tid];
#pragma unroll
            for (int m = 0; m < 64; ++m) acc[m] += aug[m * 320 + k] * w;
        }
        float b = fb1[tid];
#pragma unroll
        for (int m = 0; m < 64; ++m) hbuf[m * 256 + tid] = lrelu(acc[m] + b);
    }
    __syncthreads();

    {
        float acc[64];
#pragma unroll
        for (int m = 0; m < 64; ++m) acc[m] = 0.f;
#pragma unroll 2
        for (int k = 0; k < 256; ++k) {
            float w = fw2[k * 256 + tid];
#pragma unroll
            for (int m = 0; m < 64; ++m) acc[m] += hbuf[m * 256 + k] * w;
        }
        float b = fb2[tid];
#pragma unroll
        for (int m = 0; m < 64; ++m) aug[m * 320 + tid] = lrelu(acc[m] + b);
    }
    __syncthreads();

    {
        int c = tid & 63, sub = tid >> 6;       // 4 subs x 16 rows
        float acc3[16];
#pragma unroll
        for (int mm = 0; mm < 16; ++mm) acc3[mm] = 0.f;
#pragma unroll 2
        for (int k = 0; k < 256; ++k) {
            float w = fw3[k * 64 + c];
#pragma unroll
            for (int mm = 0; mm < 16; ++mm)
                acc3[mm] += aug[(sub * 16 + mm) * 320 + k] * w;
        }
        float b = fb3[c];
#pragma unroll
        for (int mm = 0; mm < 16; ++mm) {
            int n = row0 + sub * 16 + mm;
            int bb = n >> 11, t = (n >> 5) & 63, a = n & 31;
            if (t < 63)
                out[(((bb * 32 + a) * 63) + t) * 64 + c] = d_X[n * 64 + c] + acc3[mm] + b;
        }
    }
}

// ---------------------------------------------------------------------------
extern "C" void kernel_launch(void* const* d_in, const int* in_sizes, int n_in,
                              void* d_out, int out_size) {
    (void)in_sizes; (void)n_in; (void)out_size;
    const float* inputs    = (const float*)d_in[0];
    const float* state     = (const float*)d_in[1];
    const float* rel_type  = (const float*)d_in[2];
    const float* msg_fc1_w = (const float*)d_in[5];
    const float* msg_fc1_b = (const float*)d_in[6];
    const float* msg_fc2_w = (const float*)d_in[7];
    const float* msg_fc2_b = (const float*)d_in[8];
    const float* out_fc1_w = (const float*)d_in[9];
    const float* out_fc1_b = (const float*)d_in[10];
    const float* out_fc2_w = (const float*)d_in[11];
    const float* out_fc2_b = (const float*)d_in[12];
    const float* out_fc3_w = (const float*)d_in[13];
    const float* out_fc3_b = (const float*)d_in[14];
    float* out = (float*)d_out;

    k1x<<<(NNODE * 16 + 255) / 256, 256>>>((const float4*)inputs);
    k1g<<<(NEDGE + 255) / 256, 256>>>(state, (const float4*)rel_type);
    k2<<<NNODE / 64, 256>>>(msg_fc1_w, msg_fc1_b);
    k2w<<<dim3(8, 8, 3), dim3(32, 8)>>>(msg_fc2_w);

    cudaFuncSetAttribute(k3g, cudaFuncAttributeMaxDynamicSharedMemorySize, K3G_SMEM);
    k3g<<<147, 512, K3G_SMEM>>>(msg_fc2_b);

    cudaFuncSetAttribute(k5, cudaFuncAttributeMaxDynamicSharedMemorySize, K5_SMEM);
    k5<<<NNODE / 64, 256, K5_SMEM>>>(out_fc1_w, out_fc1_b, out_fc2_w, out_fc2_b,
                                     out_fc3_w, out_fc3_b, out);
}

// round 15
// speedup vs baseline: 1.3080x; 1.1578x over previous
#include <cuda_runtime.h>
#include <cuda_fp16.h>
#include <cstdint>

#define NNODE 8192
#define NEDGE 253952

__device__ float  d_X  [NNODE * 64];
__device__ __half d_Xh [NNODE * 64];           // fp16 copy for k2h
__device__ __half d_PQh[6 * NNODE * 256];      // [e*2+half][node][256] fp16
__device__ float  d_G  [3 * NEDGE];
__device__ float  d_AGGe[3 * NNODE * 256];     // per-expert partial agg
__device__ __half d_Wh [3 * 256 * 256];        // [e][n][k] fp16 (W2^T)
__device__ __half d_W1h[6 * 256 * 64];         // [chunk][n][k] fp16 (W1^T)

__device__ __forceinline__ float lrelu(float v) { return fmaxf(v, 0.01f * v); }

__device__ __forceinline__ uint32_t smem_u32(const void* p) {
    uint32_t a;
    asm("{ .reg .u64 t; cvta.to.shared.u64 t, %1; cvt.u32.u64 %0, t; }" : "=r"(a) : "l"(p));
    return a;
}

#define CP_ASYNC16(dst, src) \
    asm volatile("cp.async.cg.shared.global [%0], [%1], 16;" :: "r"(dst), "l"(src) : "memory")
#define CP_COMMIT() asm volatile("cp.async.commit_group;" ::: "memory")
#define CP_WAIT(n)  asm volatile("cp.async.wait_group %0;" :: "n"(n) : "memory")

#define LDSM_X4(r, a) \
    asm volatile("ldmatrix.sync.aligned.m8n8.x4.shared.b16 {%0,%1,%2,%3}, [%4];" \
        : "=r"((r)[0]), "=r"((r)[1]), "=r"((r)[2]), "=r"((r)[3]) : "r"(a))
#define MMA16816(d, a, b) \
    asm volatile("mma.sync.aligned.m16n8k16.row.col.f32.f16.f16.f32 " \
        "{%0,%1,%2,%3}, {%4,%5,%6,%7}, {%8,%9}, {%0,%1,%2,%3};" \
        : "+f"((d)[0]), "+f"((d)[1]), "+f"((d)[2]), "+f"((d)[3]) \
        : "r"((a)[0]), "r"((a)[1]), "r"((a)[2]), "r"((a)[3]), "r"((b)[0]), "r"((b)[1]))

// ------------------------- k1x: node-layout transpose (+fp16) --------------
__global__ void k1x(const float4* __restrict__ in4) {
    int idx = blockIdx.x * blockDim.x + threadIdx.x;
    if (idx >= NNODE * 16) return;
    int n = idx >> 4, q = idx & 15;
    int b = n >> 11, t = (n >> 5) & 63, a = n & 31;
    float4 v = in4[(((b * 32 + a) * 64) + t) * 16 + q];
    ((float4*)d_X)[idx] = v;
    __half2 h0 = __floats2half2_rn(v.x, v.y);
    __half2 h1 = __floats2half2_rn(v.z, v.w);
    uint2 pk; pk.x = *(uint32_t*)&h0; pk.y = *(uint32_t*)&h1;
    *(uint2*)(d_Xh + n * 64 + q * 4) = pk;
}

// ------------------------- k1g: edge gates ---------------------------------
__global__ void k1g(const float* __restrict__ state, const float4* __restrict__ rt4) {
    int idx = blockIdx.x * blockDim.x + threadIdx.x;
    if (idx >= NEDGE) return;
    int bt = idx / 992, r = idx - bt * 992;
    int b = bt >> 6, t = bt & 63;
    int rec = r / 31, j = r - rec * 31;
    int send = j + (j >= rec);
    const float4 st = *(const float4*)&state[(((b * 32 + send) * 64) + t) * 4];
    const float4* rt = rt4 + (b * 992 + r) * 4;
    float4 r0 = rt[0], r1 = rt[1], r2 = rt[2], r3 = rt[3];
    d_G[0 * NEDGE + idx] = st.x * r0.y + st.y * r1.y + st.z * r2.y + st.w * r3.y;
    d_G[1 * NEDGE + idx] = st.x * r0.z + st.y * r1.z + st.z * r2.z + st.w * r3.z;
    d_G[2 * NEDGE + idx] = st.x * r0.w + st.y * r1.w + st.z * r2.w + st.w * r3.w;
}

// --------------- k2w: W2 transpose -> fp16 [e][n][k] -----------------------
__global__ void k2w(const float* __restrict__ w2) {
    __shared__ float tile[32][33];
    int e = blockIdx.z, kt = blockIdx.x * 32, nt = blockIdx.y * 32;
    int tx = threadIdx.x, ty = threadIdx.y;          // 32 x 8
#pragma unroll
    for (int r = 0; r < 4; ++r)
        tile[ty + r * 8][tx] = w2[((size_t)(e + 1) * 256 + kt + ty + r * 8) * 256 + nt + tx];
    __syncthreads();
#pragma unroll
    for (int r = 0; r < 4; ++r) {
        int n = nt + ty + r * 8;
        d_Wh[((size_t)e * 256 + n) * 256 + kt + tx] = __float2half(tile[tx][ty + r * 8]);
    }
}

// --------------- k2wh: W1 transpose -> fp16 [chunk][n][k=64] ---------------
__global__ void k2wh(const float* __restrict__ w1) {
    __shared__ float tile[32][33];
    int chunk = blockIdx.z, kt = blockIdx.x * 32, nt = blockIdx.y * 32;
    int e = chunk >> 1, half = chunk & 1;
    int tx = threadIdx.x, ty = threadIdx.y;          // 32 x 8
#pragma unroll
    for (int r = 0; r < 4; ++r)
        tile[ty + r * 8][tx] =
            w1[((size_t)((e + 1) * 128 + half * 64 + kt + ty + r * 8)) * 256 + nt + tx];
    __syncthreads();
#pragma unroll
    for (int r = 0; r < 4; ++r) {
        int n = nt + ty + r * 8;
        d_W1h[((size_t)chunk * 256 + n) * 64 + kt + tx] = __float2half(tile[tx][ty + r * 8]);
    }
}

// --------------- k2h: P/Q node GEMMs via fp16 HMMA -------------------------
// 128 blocks x 64 rows x 256 thr (8 warps = 2M x 4N, warp tile 32x64).
// X tile (64x64 fp16) staged once; 6 W1^T chunks (256n x 64k) double-buffered.
#define X2_X    0            // 64 x 144 = 9216
#define X2_B    9216         // 2 x 256 x 144 = 73728
#define K2H_SMEM 82944

__global__ __launch_bounds__(256, 2) void k2h(const float* __restrict__ b1) {
    extern __shared__ char smem[];
    uint32_t sb = smem_u32(smem);
    int tid = threadIdx.x, lane = tid & 31, wid = tid >> 5;
    int mwarp = wid >> 2, nwarp = wid & 3;           // 2M x 4N
    int row0 = blockIdx.x * 64;

    // stage X tile (plain LDG + STS; synced by first barrier below)
    {
        int m = tid >> 2, sub = tid & 3;
        const uint4* src = (const uint4*)(d_Xh + (size_t)(row0 + m) * 64) + sub * 2;
        uint4* dst = (uint4*)(smem + X2_X + m * 144 + sub * 32);
        dst[0] = src[0]; dst[1] = src[1];
    }
    auto loadB = [&](int c) {
        uint32_t db = sb + X2_B + (uint32_t)(c & 1) * 36864u;
        const __half* S = d_W1h + (size_t)c * 16384;
        for (int i = tid; i < 2048; i += 256) {
            int n = i >> 3, g = i & 7;
            CP_ASYNC16(db + (uint32_t)(n * 144 + g * 16), (const char*)(S + n * 64 + g * 8));
        }
        CP_COMMIT();
    };
    loadB(0); loadB(1);

    uint32_t a_base = sb + X2_X
                    + (uint32_t)(mwarp * 32 + (lane & 7) + ((lane >> 3) & 1) * 8) * 144u
                    + ((lane >> 4) & 1) * 16u;

    for (int c = 0; c < 6; ++c) {
        if (c + 1 < 6) { CP_WAIT(1); } else { CP_WAIT(0); }
        __syncthreads();

        float acc[2][8][4];
#pragma unroll
        for (int ms = 0; ms < 2; ++ms)
#pragma unroll
            for (int ns = 0; ns < 8; ++ns)
#pragma unroll
                for (int q = 0; q < 4; ++q) acc[ms][ns][q] = 0.f;

        uint32_t b_base = sb + X2_B + (uint32_t)(c & 1) * 36864u
                        + (uint32_t)(nwarp * 64 + (lane & 7) + ((lane >> 4) & 1) * 8) * 144u
                        + ((lane >> 3) & 1) * 16u;
#pragma unroll
        for (int ks = 0; ks < 4; ++ks) {
            uint32_t koff = (uint32_t)(ks * 32);
            uint32_t af0[4], af1[4];
            LDSM_X4(af0, a_base + koff);
            LDSM_X4(af1, a_base + 16 * 144 + koff);
#pragma unroll
            for (int p = 0; p < 4; ++p) {
                uint32_t bf[4];
                LDSM_X4(bf, b_base + p * 2304 + koff);
                MMA16816(acc[0][2 * p],     af0, bf);
                MMA16816(acc[0][2 * p + 1], af0, bf + 2);
                MMA16816(acc[1][2 * p],     af1, bf);
                MMA16816(acc[1][2 * p + 1], af1, bf + 2);
            }
        }

        // epilogue: (+bias for half==0), fp16 store to d_PQh[c]
        {
            int eH = c >> 1;
            bool addb = (c & 1) == 0;
            __half* dstB = d_PQh + (size_t)c * NNODE * 256;
#pragma unroll
            for (int ms = 0; ms < 2; ++ms) {
                int r0 = row0 + mwarp * 32 + ms * 16 + (lane >> 2);
#pragma unroll
                for (int nst = 0; nst < 8; ++nst) {
                    int c0 = nwarp * 64 + nst * 8 + (lane & 3) * 2;
                    float b0 = addb ? __ldg(&b1[(eH + 1) * 256 + c0]) : 0.f;
                    float b1v = addb ? __ldg(&b1[(eH + 1) * 256 + c0 + 1]) : 0.f;
                    __half2 h01 = __floats2half2_rn(acc[ms][nst][0] + b0,
                                                    acc[ms][nst][1] + b1v);
                    __half2 h23 = __floats2half2_rn(acc[ms][nst][2] + b0,
                                                    acc[ms][nst][3] + b1v);
                    *(__half2*)(dstB + (size_t)r0 * 256 + c0) = h01;
                    *(__half2*)(dstB + (size_t)(r0 + 8) * 256 + c0) = h23;
                }
            }
        }
        __syncthreads();
        if (c + 2 < 6) loadB(c + 2);
    }
}

// ------------------------- k3g: B-resident fp16 HMMA edge GEMM -------------
// (unchanged from round 14: 3 x 49 blocks, 42/41 tiles, staged P/Q)
#define SB_B    0            // 256 x 528 = 135168
#define SB_A    135168       // 2 x 128 x 144 = 36864
#define SB_P    172032       // 2 x 32 x 528 = 33792
#define SB_Q    205824       // 2 x 4 x 528 = 4224
#define SB_G    210048       // 512
#define SB_B2   210560       // 1024
#define K3G_SMEM 211584

__global__ __launch_bounds__(512, 1) void k3g(const float* __restrict__ b2) {
    extern __shared__ char smem[];
    uint32_t sb = smem_u32(smem);
    int tid = threadIdx.x, lane = tid & 31, wid = tid >> 5;
    int mwarp = wid >> 2, nwarp = wid & 3;
    int e = blockIdx.x / 49, j = blockIdx.x % 49;
    int t0     = (j < 39) ? j * 42 : 39 * 42 + (j - 39) * 41;
    int ntiles = (j < 39) ? 42 : 41;

    float* g_s = (float*)(smem + SB_G);
    float* b2s = (float*)(smem + SB_B2);
    const __half* Pg = d_PQh + (size_t)(e * 2) * NNODE * 256;
    const __half* Qg = d_PQh + (size_t)(e * 2 + 1) * NNODE * 256;

    auto stageP = [&](int bt, int pb) {
        const __half* src = Pg + (size_t)bt * 32 * 256;
        for (int i = tid; i < 1024; i += 512) {
            int r = i >> 5, c = i & 31;
            CP_ASYNC16(sb + SB_P + (uint32_t)(pb * 16896 + r * 528 + c * 16),
                       (const char*)(src + r * 256 + c * 8));
        }
        CP_COMMIT();
    };
    auto stageQ = [&](int t, int qb) {
        int bt = t >> 3, a0 = (t & 7) * 4;
        const __half* src = Qg + (size_t)(bt * 32 + a0) * 256;
        if (tid < 128) {
            int r = tid >> 5, c = tid & 31;
            CP_ASYNC16(sb + SB_Q + (uint32_t)(qb * 2112 + r * 528 + c * 16),
                       (const char*)(src + r * 256 + c * 8));
        }
        CP_COMMIT();
    };
    auto stageG = [&](int t) {
        if (tid < 128) {
            int bt = t >> 3, a0 = (t & 7) * 4;
            int grp = tid >> 5, jj = tid & 31;
            g_s[tid] = (jj < 31)
                ? d_G[(size_t)e * NEDGE + bt * 992 + (a0 + grp) * 31 + jj] : 0.f;
        }
    };
    auto cvt = [](uint32_t pa, uint32_t qa) -> uint32_t {
        __half2 h = __hadd2(*(__half2*)&pa, *(__half2*)&qa);
        __half2 s = __hmul2(h, __float2half2_rn(0.01f));
        __half2 r = __hmax2(h, s);
        return *(uint32_t*)&r;
    };
    auto buildA = [&](int t, int kc, int ab, int pb, int qb) {
        int m = tid >> 2, sub = tid & 3;
        int a0 = (t & 7) * 4;
        int mq = m >> 5, jj = m & 31;
        int rec = a0 + mq;
        int send = (jj < 31) ? (jj + (jj >= rec)) : 0;   // dummy rows gated later
        const uint4* P4 = (const uint4*)(smem + SB_P + pb * 16896 + send * 528
                                         + kc * 128 + sub * 32);
        const uint4* Q4 = (const uint4*)(smem + SB_Q + qb * 2112 + mq * 528
                                         + kc * 128 + sub * 32);
        uint4 p0 = P4[0], p1 = P4[1], q0 = Q4[0], q1 = Q4[1];
        uint4 o0, o1;
        o0.x = cvt(p0.x, q0.x); o0.y = cvt(p0.y, q0.y);
        o0.z = cvt(p0.z, q0.z); o0.w = cvt(p0.w, q0.w);
        o1.x = cvt(p1.x, q1.x); o1.y = cvt(p1.y, q1.y);
        o1.z = cvt(p1.z, q1.z); o1.w = cvt(p1.w, q1.w);
        uint4* dst = (uint4*)(smem + SB_A + ab * 18432 + m * 144 + sub * 32);
        dst[0] = o0; dst[1] = o1;
    };

    if (tid < 256) b2s[tid] = b2[(e + 1) * 256 + tid];
    {
        const __half* Wsrc = d_Wh + (size_t)e * 65536;
        for (int i = tid; i < 8192; i += 512) {
            int n = i >> 5, c = i & 31;
            CP_ASYNC16(sb + SB_B + (uint32_t)(n * 528 + c * 16),
                       (const char*)(Wsrc + n * 256 + c * 8));
        }
        CP_COMMIT();
    }
    int pb = 0;
    stageP(t0 >> 3, 0);
    stageQ(t0, 0);
    CP_WAIT(0);
    __syncthreads();

    for (int ti = 0; ti < ntiles; ++ti) {
        int t = t0 + ti, qb = ti & 1;
        int bt = t >> 3, a0 = (t & 7) * 4;
        buildA(t, 0, 0, pb, qb);
        stageG(t);
        __syncthreads();

        float acc[2][8][4];
#pragma unroll
        for (int ms = 0; ms < 2; ++ms)
#pragma unroll
            for (int ns = 0; ns < 8; ++ns)
#pragma unroll
                for (int c = 0; c < 4; ++c) acc[ms][ns][c] = 0.f;

        for (int kc = 0; kc < 4; ++kc) {
            if (kc < 3) {
                buildA(t, kc + 1, (kc + 1) & 1, pb, qb);
            } else if (ti + 1 < ntiles) {
                stageQ(t + 1, qb ^ 1);
                if (((t + 1) & 7) == 0) stageP((t + 1) >> 3, pb ^ 1);
            }
            uint32_t a_l = sb + SB_A + (uint32_t)((kc & 1) * 18432)
                         + (uint32_t)(mwarp * 32 + (lane & 7) + ((lane >> 3) & 1) * 8) * 144u
                         + ((lane >> 4) & 1) * 16u;
            uint32_t b_l = sb + SB_B
                         + (uint32_t)(nwarp * 64 + (lane & 7) + ((lane >> 4) & 1) * 8) * 528u
                         + (uint32_t)(kc * 128) + ((lane >> 3) & 1) * 16u;
#pragma unroll
            for (int ks = 0; ks < 4; ++ks) {
                uint32_t af0[4], af1[4];
                LDSM_X4(af0, a_l + ks * 32);
                LDSM_X4(af1, a_l + 16 * 144 + ks * 32);
#pragma unroll
                for (int p = 0; p < 4; ++p) {
                    uint32_t bf[4];
                    LDSM_X4(bf, b_l + p * 8448 + ks * 32);
                    MMA16816(acc[0][2 * p],     af0, bf);
                    MMA16816(acc[0][2 * p + 1], af0, bf + 2);
                    MMA16816(acc[1][2 * p],     af1, bf);
                    MMA16816(acc[1][2 * p + 1], af1, bf + 2);
                }
            }
            if (kc == 3) {
                float g00 = g_s[mwarp * 32 + (lane >> 2)];
                float g01 = g_s[mwarp * 32 + (lane >> 2) + 8];
                float g10 = g_s[mwarp * 32 + 16 + (lane >> 2)];
                float g11 = g_s[mwarp * 32 + 24 + (lane >> 2)];
                int node = bt * 32 + a0 + mwarp;
#pragma unroll
                for (int nst = 0; nst < 8; ++nst) {
                    int c0 = nwarp * 64 + nst * 8 + (lane & 3) * 2;
                    float b0v = b2s[c0], b1v = b2s[c0 + 1];
                    float s0 = lrelu(acc[0][nst][0] + b0v) * g00 + lrelu(acc[0][nst][2] + b0v) * g01
                             + lrelu(acc[1][nst][0] + b0v) * g10 + lrelu(acc[1][nst][2] + b0v) * g11;
                    float s1 = lrelu(acc[0][nst][1] + b1v) * g00 + lrelu(acc[0][nst][3] + b1v) * g01
                             + lrelu(acc[1][nst][1] + b1v) * g10 + lrelu(acc[1][nst][3] + b1v) * g11;
                    s0 += __shfl_xor_sync(~0u, s0, 4);  s1 += __shfl_xor_sync(~0u, s1, 4);
                    s0 += __shfl_xor_sync(~0u, s0, 8);  s1 += __shfl_xor_sync(~0u, s1, 8);
                    s0 += __shfl_xor_sync(~0u, s0, 16); s1 += __shfl_xor_sync(~0u, s1, 16);
                    if (lane < 4) {
                        float2 o; o.x = s0; o.y = s1;
                        *(float2*)(d_AGGe + ((size_t)e * NNODE + node) * 256 + c0) = o;
                    }
                }
                if (ti + 1 < ntiles) CP_WAIT(0);
            }
            __syncthreads();
        }
        if (((t + 1) & 7) == 0) pb ^= 1;
    }
}

// --------- k5: output MLP + residual (64-row blocks, unchanged) ------------
#define K5_SMEM (64 * 320 * 4 + 64 * 256 * 4)   // aug + hbuf = 147456

__global__ __launch_bounds__(256) void k5(const float* __restrict__ fw1,
                                          const float* __restrict__ fb1,
                                          const float* __restrict__ fw2,
                                          const float* __restrict__ fb2,
                                          const float* __restrict__ fw3,
                                          const float* __restrict__ fb3,
                                          float* __restrict__ out) {
    extern __shared__ float sm5[];
    float* aug  = sm5;               // [64][320]
    float* hbuf = sm5 + 64 * 320;    // [64][256]
    int row0 = blockIdx.x * 64, tid = threadIdx.x;

    for (int i = tid; i < 64 * 64; i += 256)
        aug[(i >> 6) * 320 + (i & 63)] = d_X[row0 * 64 + i];
    for (int i = tid; i < 64 * 256; i += 256) {
        size_t base = (size_t)row0 * 256 + i;
        aug[(i >> 8) * 320 + 64 + (i & 255)] = d_AGGe[base]
                                             + d_AGGe[(size_t)NNODE * 256 + base]
                                             + d_AGGe[(size_t)2 * NNODE * 256 + base];
    }
    __syncthreads();

    {
        float acc[64];
#pragma unroll
        for (int m = 0; m < 64; ++m) acc[m] = 0.f;
#pragma unroll 2
        for (int k = 0; k < 320; ++k) {
            float w = fw1[k * 256 + tid];
#pragma unroll
            for (int m = 0; m < 64; ++m) acc[m] += aug[m * 320 + k] * w;
        }
        float b = fb1[tid];
#pragma unroll
        for (int m = 0; m < 64; ++m) hbuf[m * 256 + tid] = lrelu(acc[m] + b);
    }
    __syncthreads();

    {
        float acc[64];
#pragma unroll
        for (int m = 0; m < 64; ++m) acc[m] = 0.f;
#pragma unroll 2
        for (int k = 0; k < 256; ++k) {
            float w = fw2[k * 256 + tid];
#pragma unroll
            for (int m = 0; m < 64; ++m) acc[m] += hbuf[m * 256 + k] * w;
        }
        float b = fb2[tid];
#pragma unroll
        for (int m = 0; m < 64; ++m) aug[m * 320 + tid] = lrelu(acc[m] + b);
    }
    __syncthreads();

    {
        int c = tid & 63, sub = tid >> 6;       // 4 subs x 16 rows
        float acc3[16];
#pragma unroll
        for (int mm = 0; mm < 16; ++mm) acc3[mm] = 0.f;
#pragma unroll 2
        for (int k = 0; k < 256; ++k) {
            float w = fw3[k * 64 + c];
#pragma unroll
            for (int mm = 0; mm < 16; ++mm)
                acc3[mm] += aug[(sub * 16 + mm) * 320 + k] * w;
        }
        float b = fb3[c];
#pragma unroll
        for (int mm = 0; mm < 16; ++mm) {
            int n = row0 + sub * 16 + mm;
            int bb = n >> 11, t = (n >> 5) & 63, a = n & 31;
            if (t < 63)
                out[(((bb * 32 + a) * 63) + t) * 64 + c] = d_X[n * 64 + c] + acc3[mm] + b;
        }
    }
}

// ---------------------------------------------------------------------------
extern "C" void kernel_launch(void* const* d_in, const int* in_sizes, int n_in,
                              void* d_out, int out_size) {
    (void)in_sizes; (void)n_in; (void)out_size;
    const float* inputs    = (const float*)d_in[0];
    const float* state     = (const float*)d_in[1];
    const float* rel_type  = (const float*)d_in[2];
    const float* msg_fc1_w = (const float*)d_in[5];
    const float* msg_fc1_b = (const float*)d_in[6];
    const float* msg_fc2_w = (const float*)d_in[7];
    const float* msg_fc2_b = (const float*)d_in[8];
    const float* out_fc1_w = (const float*)d_in[9];
    const float* out_fc1_b = (const float*)d_in[10];
    const float* out_fc2_w = (const float*)d_in[11];
    const float* out_fc2_b = (const float*)d_in[12];
    const float* out_fc3_w = (const float*)d_in[13];
    const float* out_fc3_b = (const float*)d_in[14];
    float* out = (float*)d_out;

    k1x<<<(NNODE * 16 + 255) / 256, 256>>>((const float4*)inputs);
    k1g<<<(NEDGE + 255) / 256, 256>>>(state, (const float4*)rel_type);
    k2w<<<dim3(8, 8, 3), dim3(32, 8)>>>(msg_fc2_w);
    k2wh<<<dim3(2, 8, 6), dim3(32, 8)>>>(msg_fc1_w);

    cudaFuncSetAttribute(k2h, cudaFuncAttributeMaxDynamicSharedMemorySize, K2H_SMEM);
    k2h<<<NNODE / 64, 256, K2H_SMEM>>>(msg_fc1_b);

    cudaFuncSetAttribute(k3g, cudaFuncAttributeMaxDynamicSharedMemorySize, K3G_SMEM);
    k3g<<<147, 512, K3G_SMEM>>>(msg_fc2_b);

    cudaFuncSetAttribute(k5, cudaFuncAttributeMaxDynamicSharedMemorySize, K5_SMEM);
    k5<<<NNODE / 64, 256, K5_SMEM>>>(out_fc1_w, out_fc1_b, out_fc2_w, out_fc2_b,
                                     out_fc3_w, out_fc3_b, out);
}